// round 1
// baseline (speedup 1.0000x reference)
#include <cuda_runtime.h>

// depthconv1d: B=8, L=16384, C=512, K=31, SAME padding, fp32 NWC.
// out[b,w,c] = sum_k x[b, w+k-15, c] * ker[k*C + c] + bias[c]
//
// Strategy: f32x2 packed FMA (FFMA2) — 2 channels per thread, sliding tile of
// T=16 output positions per thread, weights resident in registers.

#define B_ 8
#define L_ 16384
#define C_ 512
#define K_ 31
#define HALF_ 15
#define T_ 16   // output positions per thread

using u64 = unsigned long long;

__device__ __forceinline__ u64 fma2(u64 a, u64 b, u64 c) {
    u64 d;
    asm("fma.rn.f32x2 %0, %1, %2, %3;" : "=l"(d) : "l"(a), "l"(b), "l"(c));
    return d;
}
__device__ __forceinline__ u64 add2(u64 a, u64 b) {
    u64 d;
    asm("add.rn.f32x2 %0, %1, %2;" : "=l"(d) : "l"(a), "l"(b));
    return d;
}

template <bool EDGE>
__device__ __forceinline__ void conv_body(
    const float* __restrict__ x, const float* __restrict__ w,
    const float* __restrict__ bias, float* __restrict__ out,
    int b, int w0, int cb)
{
    // Per-thread packed weights: ker[k*C + cb .. cb+1] as one 64-bit value.
    u64 wk[K_];
#pragma unroll
    for (int k = 0; k < K_; k++)
        wk[k] = *reinterpret_cast<const u64*>(w + k * C_ + cb);

    u64 acc[T_];
#pragma unroll
    for (int t = 0; t < T_; t++) acc[t] = 0ull;

    // Base pointer at (b, w0 - HALF, cb). Row stride = C_ floats = 2048 B.
    const char* xb = reinterpret_cast<const char*>(x)
                   + ((long long)((long long)b * L_ + w0 - HALF_) * C_ + cb) * 4ll;

    // Stream T_+K_-1 = 46 input rows; each feeds up to 31 outputs.
#pragma unroll
    for (int p = 0; p < T_ + K_ - 1; p++) {
        u64 xv;
        if (EDGE) {
            int wg = w0 - HALF_ + p;
            xv = (wg >= 0 && wg < L_)
                 ? *reinterpret_cast<const u64*>(xb + (long long)p * C_ * 4ll)
                 : 0ull;
        } else {
            xv = *reinterpret_cast<const u64*>(xb + (long long)p * C_ * 4ll);
        }
#pragma unroll
        for (int t = 0; t < T_; t++) {
            int k = p - t;
            if (k >= 0 && k < K_)
                acc[t] = fma2(xv, wk[k], acc[t]);
        }
    }

    u64 bv = *reinterpret_cast<const u64*>(bias + cb);
#pragma unroll
    for (int t = 0; t < T_; t++) {
        u64 r = add2(acc[t], bv);
        *reinterpret_cast<u64*>(
            out + ((long long)((long long)b * L_ + w0 + t) * C_ + cb)) = r;
    }
}

__global__ __launch_bounds__(256, 2)
void depthconv1d_kernel(const float* __restrict__ x,
                        const float* __restrict__ w,
                        const float* __restrict__ bias,
                        float* __restrict__ out)
{
    int cb   = threadIdx.x * 2;        // channel pair base (0..510)
    int tile = blockIdx.x;             // L tile index
    int b    = blockIdx.y;             // batch
    int w0   = tile * T_;

    if (tile == 0 || tile == (L_ / T_ - 1))
        conv_body<true>(x, w, bias, out, b, w0, cb);
    else
        conv_body<false>(x, w, bias, out, b, w0, cb);
}

extern "C" void kernel_launch(void* const* d_in, const int* in_sizes, int n_in,
                              void* d_out, int out_size)
{
    const float* x    = (const float*)d_in[0];  // [8, 16384, 512]
    const float* ker  = (const float*)d_in[1];  // [31, 512, 1]
    const float* bias = (const float*)d_in[2];  // [512]
    float* out = (float*)d_out;                 // [8, 16384, 512]

    dim3 grid(L_ / T_, B_);   // (1024, 8)
    dim3 block(256);          // 2 channels per thread -> 512 channels
    depthconv1d_kernel<<<grid, block>>>(x, ker, bias, out);
}